// round 14
// baseline (speedup 1.0000x reference)
#include <cuda_runtime.h>
#include <cuda_bf16.h>
#include <cstdint>

#define NE   8192
#define DD   64
#define NTOK 16384
#define BETA  0.25f
#define DECAY 0.99f
#define EPSC  1e-5f

// output layout (concatenated, float32)
#define OZQ   0
#define OLOSS 1048576
#define OW    1048577
#define OCS   1572865
#define OEA   1581057

#define MARGIN 6.0f

// ------------------------------------------------------------- device scratch
__device__ float g_wsq[NE];
__device__ float g_enc[NE];
__device__ float g_emb[NE * DD];
__device__ float g_loss;
__device__ float g_nsum;
__device__ __nv_bfloat16 g_w1[NE * DD];

// ------------------------------------------------------------- helpers
__device__ __forceinline__ uint32_t smem_u32(const void* p) {
    uint32_t a;
    asm("{ .reg .u64 t; cvta.to.shared.u64 t, %1; cvt.u32.u64 %0, t; }" : "=r"(a) : "l"(p));
    return a;
}
#define SWZ(b) ((b) ^ (((b) >> 3) & 0x70))

#define LDMX4(r0, r1, r2, r3, a) \
    asm volatile("ldmatrix.sync.aligned.m8n8.x4.shared.b16 {%0,%1,%2,%3}, [%4];" \
                 : "=r"(r0), "=r"(r1), "=r"(r2), "=r"(r3) : "r"(a))

#define MMA16816(d, a, b0, b1) \
    asm volatile("mma.sync.aligned.m16n8k16.row.col.f32.bf16.bf16.f32 " \
                 "{%0,%1,%2,%3},{%4,%5,%6,%7},{%8,%9},{%0,%1,%2,%3};" \
                 : "+f"((d)[0]), "+f"((d)[1]), "+f"((d)[2]), "+f"((d)[3]) \
                 : "r"((a)[0]), "r"((a)[1]), "r"((a)[2]), "r"((a)[3]), \
                   "r"(b0), "r"(b1))

#define CP_ASYNC16(dst, src) \
    asm volatile("cp.async.cg.shared.global [%0], [%1], 16;" :: "r"(dst), "l"(src))
#define CP_COMMIT() asm volatile("cp.async.commit_group;" ::: "memory")

// ------------------------------------------------------------- prep: zero + bf16 w
__global__ void k_prep(const float* __restrict__ w) {
    int i = blockIdx.x * blockDim.x + threadIdx.x;
    if (i < NE * DD) { g_emb[i] = 0.f; g_w1[i] = __float2bfloat16(w[i]); }
    if (i < NE) g_enc[i] = 0.f;
    if (i == 0) { g_loss = 0.f; g_nsum = 0.f; }
}

// ------------------------------------------------------------- |w_k|^2 (fp32 exact)
__global__ void k_wsq(const float* __restrict__ w) {
    int gt   = blockIdx.x * blockDim.x + threadIdx.x;
    int row  = gt >> 5;
    int lane = gt & 31;
    if (row >= NE) return;
    const float* r = w + row * DD;
    float a = r[lane], b2 = r[lane + 32];
    float s = a * a + b2 * b2;
    #pragma unroll
    for (int o = 16; o; o >>= 1) s += __shfl_down_sync(0xFFFFFFFFu, s, o);
    if (lane == 0) g_wsq[row] = s;
}

// ------------------------------------------------------------- fused main kernel
// smem layout (bytes)
#define SM_A    0                 // 16 KB  A bf16 swizzled (overlaid by WT in refine)
#define SM_B    16384             // 32 KB  B double buffer (overlaid by WT in refine)
#define SM_WSQ  49152             // 32 KB  wsq[8192] f32
#define SM_Z    81920             // 33.8KB z fp32 [c][t], pitch 132 (ends 115712)
#define SM_TMIN 115712            // 32 KB  per-(token,tile) coarse min
#define SM_THR  148480            // 512 B  per-token threshold
#define SM_KEY  148992            // 1 KB   per-token u64 (score,k)
#define SM_IDX  150016            // 512 B  per-token best k
#define SM_HIT  150528            // 4 B cnt + 128*4 B list
#define SM_TOT  151072

__device__ __forceinline__ void load_b_tile(uint32_t smb, int t, int buf, int tid) {
    #pragma unroll
    for (int i = 0; i < 4; i++) {
        int idx = i * 256 + tid;
        int row = idx >> 3, c = idx & 7;
        uint32_t dst = smb + SM_B + buf * 16384 + SWZ(row * 128 + c * 16);
        const void* src = g_w1 + (t * 128 + row) * 64 + c * 8;
        CP_ASYNC16(dst, src);
    }
    CP_COMMIT();
}

__global__ __launch_bounds__(256) void k_main(const float* __restrict__ z,
                                              const float* __restrict__ w,
                                              float* __restrict__ out) {
    extern __shared__ char sm[];
    uint32_t smb = smem_u32(sm);
    const int tid = threadIdx.x, lane = tid & 31, wp = tid >> 5;
    const int tok0 = blockIdx.x * 128;
    const int b = tok0 >> 10, hw0 = tok0 & 1023;

    float* zsm  = reinterpret_cast<float*>(sm + SM_Z);
    float* wsq  = reinterpret_cast<float*>(sm + SM_WSQ);
    float* tmin = reinterpret_cast<float*>(sm + SM_TMIN);
    float* thr  = reinterpret_cast<float*>(sm + SM_THR);
    unsigned long long* skey = reinterpret_cast<unsigned long long*>(sm + SM_KEY);
    int* sidx = reinterpret_cast<int*>(sm + SM_IDX);
    int* hitc = reinterpret_cast<int*>(sm + SM_HIT);
    int* hitl = hitc + 1;

    // prefetch first two B tiles while we stage everything else
    load_b_tile(smb, 0, 0, tid);
    load_b_tile(smb, 1, 1, tid);

    // wsq -> smem (32 KB)
    #pragma unroll
    for (int i = 0; i < 8; i++) {
        int idx = i * 256 + tid;
        reinterpret_cast<uint4*>(wsq)[idx] = reinterpret_cast<const uint4*>(g_wsq)[idx];
    }
    // z fp32 -> smem, channel-major [c][t] (coalesced global reads)
    #pragma unroll
    for (int i = 0; i < 32; i++) {
        int idx = i * 256 + tid;
        int c = idx >> 7, t = idx & 127;
        zsm[c * 132 + t] = z[b * 65536 + c * 1024 + hw0 + t];
    }
    if (tid < 128) skey[tid] = ~0ull;
    __syncthreads();

    // build bf16 A tile (swizzled) from the fp32 z tile
    #pragma unroll
    for (int i = 0; i < 4; i++) {
        int idx = i * 256 + tid;
        int t = idx >> 3, c8 = idx & 7;
        uint32_t pk[4];
        #pragma unroll
        for (int u = 0; u < 4; u++) {
            float f0 = zsm[(c8 * 8 + 2 * u)     * 132 + t];
            float f1 = zsm[(c8 * 8 + 2 * u + 1) * 132 + t];
            __nv_bfloat162 h = __floats2bfloat162_rn(f0, f1);
            pk[u] = *reinterpret_cast<uint32_t*>(&h);
        }
        *reinterpret_cast<uint4*>(sm + SM_A + SWZ(t * 128 + c8 * 16)) =
            make_uint4(pk[0], pk[1], pk[2], pk[3]);
    }
    __syncthreads();

    // A fragments (resident in registers for the whole loop)
    uint32_t afr[4][4];
    {
        int grp = lane >> 3, lr = lane & 7;
        #pragma unroll
        for (int c = 0; c < 4; c++) {
            int row = wp * 16 + ((grp & 1) ? 8 : 0) + lr;
            int kb  = c * 32 + ((grp & 2) ? 16 : 0);
            uint32_t ad = smb + SM_A + SWZ(row * 128 + kb);
            LDMX4(afr[c][0], afr[c][1], afr[c][2], afr[c][3], ad);
        }
    }

    const int q = lane & 3, r = lane >> 2;
    const int tt0 = wp * 16 + r;              // this thread's tokens: tt0, tt0+8
    const int lr = lane & 7, grp = lane >> 3;
    const int koff = (grp & 1) * 16 + (grp >> 1) * 32;

    // =================== single GEMM pass: per-(token,tile) min ===================
    #pragma unroll 1
    for (int t = 0; t < 64; t++) {
        if (t < 63) asm volatile("cp.async.wait_group 1;" ::: "memory");
        else        asm volatile("cp.async.wait_group 0;" ::: "memory");
        __syncthreads();

        uint32_t bb = smb + SM_B + (t & 1) * 16384;
        float acc[16][4];
        #pragma unroll
        for (int j = 0; j < 16; j++)
            #pragma unroll
            for (int e = 0; e < 4; e++) acc[j][e] = 0.f;

        #pragma unroll
        for (int j = 0; j < 16; j++) {
            int rowb = j * 8 + lr;
            uint32_t b0, b1, b2, b3, b4, b5, b6, b7;
            LDMX4(b0, b1, b2, b3, bb + SWZ(rowb * 128 + koff));
            LDMX4(b4, b5, b6, b7, bb + SWZ(rowb * 128 + 64 + koff));
            MMA16816(acc[j], afr[0], b0, b1);
            MMA16816(acc[j], afr[1], b2, b3);
            MMA16816(acc[j], afr[2], b4, b5);
            MMA16816(acc[j], afr[3], b6, b7);
        }
        __syncthreads();                     // all reads of buf (t&1) done
        if (t + 2 < 64) load_b_tile(smb, t + 2, t & 1, tid);

        // epilogue: fp32 scores -> per-(token,tile) min
        float m0 = 3.4e38f, m1 = 3.4e38f;
        #pragma unroll
        for (int j = 0; j < 16; j++) {
            int col = t * 128 + j * 8 + 2 * q;
            float w0 = wsq[col], w1v = wsq[col + 1];
            m0 = fminf(m0, fminf(fmaf(acc[j][0], -2.f, w0),
                                 fmaf(acc[j][1], -2.f, w1v)));
            m1 = fminf(m1, fminf(fmaf(acc[j][2], -2.f, w0),
                                 fmaf(acc[j][3], -2.f, w1v)));
        }
        #pragma unroll
        for (int o = 1; o <= 2; o <<= 1) {
            m0 = fminf(m0, __shfl_xor_sync(0xFFFFFFFFu, m0, o));
            m1 = fminf(m1, __shfl_xor_sync(0xFFFFFFFFu, m1, o));
        }
        if (q == 0) {
            tmin[tt0 * 64 + t]       = m0;
            tmin[(tt0 + 8) * 64 + t] = m1;
        }
    }
    __syncthreads();

    // per-token threshold = min over tiles + MARGIN
    if (tid < 128) {
        float m = 3.4e38f;
        #pragma unroll 1
        for (int t = 0; t < 64; t++) m = fminf(m, tmin[tid * 64 + t]);
        thr[tid] = m + MARGIN;
    }
    __syncthreads();

    // =================== tile-granular exact refinement ===================
    float* wt = reinterpret_cast<float*>(sm);   // overlays dead A+B (33.3 KB < 48 KB)
    #pragma unroll 1
    for (int t = 0; t < 64; t++) {
        if (tid == 0) hitc[0] = 0;
        __syncthreads();
        if (tid < 128 && tmin[tid * 64 + t] < thr[tid]) {
            int s = atomicAdd(hitc, 1);
            hitl[s] = tid;
        }
        __syncthreads();
        int m = hitc[0];
        if (m > 0) {
            // stage w tile t transposed: wt[c*130 + k], k in [0,128)
            const float4* wg = reinterpret_cast<const float4*>(w) + t * 128 * 16;
            #pragma unroll 1
            for (int ii = 0; ii < 8; ii++) {
                int i = ii * 256 + tid;
                int row = i >> 4, c4 = i & 15;
                float4 v = __ldg(wg + row * 16 + c4);
                wt[(c4 * 4 + 0) * 130 + row] = v.x;
                wt[(c4 * 4 + 1) * 130 + row] = v.y;
                wt[(c4 * 4 + 2) * 130 + row] = v.z;
                wt[(c4 * 4 + 3) * 130 + row] = v.w;
            }
            __syncthreads();
            int total = m * 128;
            #pragma unroll 1
            for (int s = tid; s < total; s += 256) {
                int token = hitl[s >> 7];
                int k = s & 127;
                float dot = 0.f;
                #pragma unroll
                for (int c = 0; c < 64; c++)
                    dot = fmaf(zsm[c * 132 + token], wt[c * 130 + k], dot);
                float d = fmaf(dot, -2.f, wsq[t * 128 + k]);
                uint32_t u = __float_as_uint(d);
                u ^= (u & 0x80000000u) ? 0xFFFFFFFFu : 0x80000000u;
                unsigned long long key =
                    ((unsigned long long)u << 32) | (uint32_t)(t * 128 + k);
                atomicMin(&skey[token], key);
            }
            __syncthreads();
        }
    }
    __syncthreads();
    if (tid < 128) sidx[tid] = (int)(skey[tid] & 0xFFFFFFFFull);
    __syncthreads();

    // ---------------- fused combine: z_q scatter, loss, segment sums ----------------
    float lsum = 0.f;
    #pragma unroll 1
    for (int i = tid; i < 8192; i += 256) {
        int tt = i & 127, c = i >> 7;
        int k = sidx[tt];
        float zv = zsm[c * 132 + tt];
        float wv = __ldg(w + k * 64 + c);
        out[OZQ + b * 65536 + c * 1024 + hw0 + tt] = wv;
        float dd = wv - zv;
        lsum += dd * dd;
        atomicAdd(&g_emb[k * 64 + c], zv);
    }
    #pragma unroll
    for (int o = 16; o; o >>= 1) lsum += __shfl_down_sync(0xFFFFFFFFu, lsum, o);
    if (lane == 0) atomicAdd(&g_loss, lsum);
    if (tid < 128) atomicAdd(&g_enc[sidx[tid]], 1.0f);
}

// ------------------------------------------------------------- EMA stage 1
__global__ void k_ema1(const float* __restrict__ cs,
                       const float* __restrict__ ea,
                       float* __restrict__ out) {
    int i = blockIdx.x * blockDim.x + threadIdx.x;
    if (i < NE * DD)
        out[OEA + i] = ea[i] * DECAY + (1.f - DECAY) * g_emb[i];
    float v = 0.f;
    if (i < NE) {
        v = cs[i] * DECAY + (1.f - DECAY) * g_enc[i];
        out[OCS + i] = v;
    }
    #pragma unroll
    for (int o = 16; o; o >>= 1) v += __shfl_down_sync(0xFFFFFFFFu, v, o);
    if ((threadIdx.x & 31) == 0 && i < NE) atomicAdd(&g_nsum, v);
}

// ------------------------------------------------------------- EMA stage 2
__global__ void k_ema2(float* __restrict__ out) {
    int i = blockIdx.x * blockDim.x + threadIdx.x;
    float nn = g_nsum;
    int k = i >> 6;
    float ncs = out[OCS + k];
    float sm  = (ncs + EPSC) / (nn + (float)NE * EPSC) * nn;
    out[OW + i] = out[OEA + i] / sm;
    if (i == 0) out[OLOSS] = BETA * g_loss / (float)(NTOK * DD);
}

// ------------------------------------------------------------- launch
extern "C" void kernel_launch(void* const* d_in, const int* in_sizes, int n_in,
                              void* d_out, int out_size) {
    const float* z  = (const float*)d_in[0];
    const float* w  = (const float*)d_in[1];
    const float* cs = (const float*)d_in[2];
    const float* ea = (const float*)d_in[3];
    float* out = (float*)d_out;

    cudaFuncSetAttribute(k_main, cudaFuncAttributeMaxDynamicSharedMemorySize, SM_TOT);

    k_prep <<<(NE * DD + 255) / 256, 256>>>(w);
    k_wsq  <<<(NE * 32) / 256, 256>>>(w);
    k_main <<<NTOK / 128, 256, SM_TOT>>>(z, w, out);
    k_ema1 <<<(NE * DD) / 256, 256>>>(cs, ea, out);
    k_ema2 <<<(NE * DD) / 256, 256>>>(out);
}

// round 15
// speedup vs baseline: 1.8858x; 1.8858x over previous
#include <cuda_runtime.h>
#include <cuda_bf16.h>
#include <cstdint>

#define NE   8192
#define DD   64
#define NTOK 16384
#define BETA  0.25f
#define DECAY 0.99f
#define EPSC  1e-5f

// output layout (concatenated, float32)
#define OZQ   0
#define OLOSS 1048576
#define OW    1048577
#define OCS   1572865
#define OEA   1581057

#define MARGIN 6.0f
#define CAP    4096
#define SEED   4          // seed tiles before recording starts
#define NITER  (64 + SEED)

// ------------------------------------------------------------- device scratch
__device__ float g_wsq[NE];
__device__ float g_enc[NE];
__device__ float g_emb[NE * DD];
__device__ float g_loss;
__device__ float g_nsum;
__device__ __nv_bfloat16 g_w1[NE * DD];

// ------------------------------------------------------------- helpers
__device__ __forceinline__ uint32_t smem_u32(const void* p) {
    uint32_t a;
    asm("{ .reg .u64 t; cvta.to.shared.u64 t, %1; cvt.u32.u64 %0, t; }" : "=r"(a) : "l"(p));
    return a;
}
#define SWZ(b) ((b) ^ (((b) >> 3) & 0x70))

#define LDMX4(r0, r1, r2, r3, a) \
    asm volatile("ldmatrix.sync.aligned.m8n8.x4.shared.b16 {%0,%1,%2,%3}, [%4];" \
                 : "=r"(r0), "=r"(r1), "=r"(r2), "=r"(r3) : "r"(a))

#define MMA16816(d, a, b0, b1) \
    asm volatile("mma.sync.aligned.m16n8k16.row.col.f32.bf16.bf16.f32 " \
                 "{%0,%1,%2,%3},{%4,%5,%6,%7},{%8,%9},{%0,%1,%2,%3};" \
                 : "+f"((d)[0]), "+f"((d)[1]), "+f"((d)[2]), "+f"((d)[3]) \
                 : "r"((a)[0]), "r"((a)[1]), "r"((a)[2]), "r"((a)[3]), \
                   "r"(b0), "r"(b1))

#define CP_ASYNC16(dst, src) \
    asm volatile("cp.async.cg.shared.global [%0], [%1], 16;" :: "r"(dst), "l"(src))
#define CP_COMMIT() asm volatile("cp.async.commit_group;" ::: "memory")

// ------------------------------------------------------------- prep: zero + bf16 w
__global__ void k_prep(const float* __restrict__ w) {
    int i = blockIdx.x * blockDim.x + threadIdx.x;
    if (i < NE * DD) { g_emb[i] = 0.f; g_w1[i] = __float2bfloat16(w[i]); }
    if (i < NE) g_enc[i] = 0.f;
    if (i == 0) { g_loss = 0.f; g_nsum = 0.f; }
}

// ------------------------------------------------------------- |w_k|^2 (fp32 exact)
__global__ void k_wsq(const float* __restrict__ w) {
    int gt   = blockIdx.x * blockDim.x + threadIdx.x;
    int row  = gt >> 5;
    int lane = gt & 31;
    if (row >= NE) return;
    const float* r = w + row * DD;
    float a = r[lane], b2 = r[lane + 32];
    float s = a * a + b2 * b2;
    #pragma unroll
    for (int o = 16; o; o >>= 1) s += __shfl_down_sync(0xFFFFFFFFu, s, o);
    if (lane == 0) g_wsq[row] = s;
}

// ------------------------------------------------------------- fused main kernel
// smem layout (bytes)
#define SM_A    0                 // 16 KB  A bf16 swizzled
#define SM_B    16384             // 32 KB  B double buffer
#define SM_WSQ  49152             // 32 KB  wsq[8192]
#define SM_Z    81920             // 33 KB  z fp32 [c][t], pitch 132
#define SM_KEY  115712            // 1 KB   per-token u64 (score,k) keys
#define SM_IDX  116736            // 512 B  per-token best k
#define SM_CAND 117248            // 16 KB  candidate buffer
#define SM_CNT  133632            // 8 B    counter
#define SM_TOT  133664

__device__ __forceinline__ void load_b_tile(uint32_t smb, int t, int buf, int tid) {
    #pragma unroll
    for (int i = 0; i < 4; i++) {
        int idx = i * 256 + tid;
        int row = idx >> 3, c = idx & 7;
        uint32_t dst = smb + SM_B + buf * 16384 + SWZ(row * 128 + c * 16);
        const void* src = g_w1 + (t * 128 + row) * 64 + c * 8;
        CP_ASYNC16(dst, src);
    }
    CP_COMMIT();
}

// exact fp32 rescore of (token tt, code k) -> atomicMin into shared key
__device__ __forceinline__ void refine_to(unsigned long long* skey, const float* zsm,
                                          const float* __restrict__ w, const float* wsq,
                                          int tt, int k) {
    const float4* wr = reinterpret_cast<const float4*>(w + k * DD);
    float dot = 0.f;
    #pragma unroll
    for (int c4 = 0; c4 < 16; c4++) {
        float4 wv = __ldg(wr + c4);
        dot = fmaf(zsm[(c4 * 4 + 0) * 132 + tt], wv.x, dot);
        dot = fmaf(zsm[(c4 * 4 + 1) * 132 + tt], wv.y, dot);
        dot = fmaf(zsm[(c4 * 4 + 2) * 132 + tt], wv.z, dot);
        dot = fmaf(zsm[(c4 * 4 + 3) * 132 + tt], wv.w, dot);
    }
    float d = fmaf(dot, -2.f, wsq[k]);
    uint32_t u = __float_as_uint(d);
    u ^= (u & 0x80000000u) ? 0xFFFFFFFFu : 0x80000000u;
    unsigned long long key = ((unsigned long long)u << 32) | (uint32_t)k;
    atomicMin(&skey[tt], key);
}

__global__ __launch_bounds__(256) void k_main(const float* __restrict__ z,
                                              const float* __restrict__ w,
                                              float* __restrict__ out) {
    extern __shared__ char sm[];
    uint32_t smb = smem_u32(sm);
    const int tid = threadIdx.x, lane = tid & 31, wp = tid >> 5;
    const int tok0 = blockIdx.x * 128;
    const int b = tok0 >> 10, hw0 = tok0 & 1023;

    float* zsm  = reinterpret_cast<float*>(sm + SM_Z);
    float* wsq  = reinterpret_cast<float*>(sm + SM_WSQ);
    int*   sidx = reinterpret_cast<int*>(sm + SM_IDX);
    unsigned long long* skey = reinterpret_cast<unsigned long long*>(sm + SM_KEY);
    uint32_t* scand = reinterpret_cast<uint32_t*>(sm + SM_CAND);
    int* scnt = reinterpret_cast<int*>(sm + SM_CNT);

    // prefetch first two B tiles while we stage everything else
    load_b_tile(smb, 0, 0, tid);
    load_b_tile(smb, 1, 1, tid);

    // wsq -> smem (32 KB)
    #pragma unroll
    for (int i = 0; i < 8; i++) {
        int idx = i * 256 + tid;
        reinterpret_cast<uint4*>(wsq)[idx] = reinterpret_cast<const uint4*>(g_wsq)[idx];
    }
    // z fp32 -> smem, channel-major [c][t] (coalesced global reads)
    #pragma unroll
    for (int i = 0; i < 32; i++) {
        int idx = i * 256 + tid;
        int c = idx >> 7, t = idx & 127;
        zsm[c * 132 + t] = z[b * 65536 + c * 1024 + hw0 + t];
    }
    if (tid < 128) skey[tid] = ~0ull;
    if (tid == 0) scnt[0] = 0;
    __syncthreads();

    // build bf16 A tile (swizzled) from the fp32 z tile
    #pragma unroll
    for (int i = 0; i < 4; i++) {
        int idx = i * 256 + tid;
        int t = idx >> 3, c8 = idx & 7;
        uint32_t pk[4];
        #pragma unroll
        for (int u = 0; u < 4; u++) {
            float f0 = zsm[(c8 * 8 + 2 * u)     * 132 + t];
            float f1 = zsm[(c8 * 8 + 2 * u + 1) * 132 + t];
            __nv_bfloat162 h = __floats2bfloat162_rn(f0, f1);
            pk[u] = *reinterpret_cast<uint32_t*>(&h);
        }
        *reinterpret_cast<uint4*>(sm + SM_A + SWZ(t * 128 + c8 * 16)) =
            make_uint4(pk[0], pk[1], pk[2], pk[3]);
    }
    __syncthreads();

    // A fragments (resident in registers for the whole loop)
    uint32_t afr[4][4];
    {
        int grp = lane >> 3, lr = lane & 7;
        #pragma unroll
        for (int c = 0; c < 4; c++) {
            int row = wp * 16 + ((grp & 1) ? 8 : 0) + lr;
            int kb  = c * 32 + ((grp & 2) ? 16 : 0);
            uint32_t ad = smb + SM_A + SWZ(row * 128 + kb);
            LDMX4(afr[c][0], afr[c][1], afr[c][2], afr[c][3], ad);
        }
    }

    const int q = lane & 3, r = lane >> 2;
    const int tt0 = wp * 16 + r;              // this thread's tokens: tt0, tt0+8
    const int lr = lane & 7, grp = lane >> 3;
    const int koff = (grp & 1) * 16 + (grp >> 1) * 32;

    // =================== single GEMM pass (68 iters: 64 tiles + 4-tile replay) =====
    // tiles 0..SEED-1 seed the running min (no recording); tiles SEED..63 record
    // against the quad-reduced running threshold; tiles 0..SEED-1 replay at the
    // end (t=64..67) so their codes are recorded with the final threshold.
    float run0 = 3.4e38f, run1 = 3.4e38f;
    float thr0 = -3.4e38f, thr1 = -3.4e38f;

    #pragma unroll 1
    for (int t = 0; t < NITER; t++) {
        if (t < NITER - 1) asm volatile("cp.async.wait_group 1;" ::: "memory");
        else               asm volatile("cp.async.wait_group 0;" ::: "memory");
        __syncthreads();

        uint32_t bb = smb + SM_B + (t & 1) * 16384;
        float acc[16][4];
        #pragma unroll
        for (int j = 0; j < 16; j++)
            #pragma unroll
            for (int e = 0; e < 4; e++) acc[j][e] = 0.f;

        #pragma unroll
        for (int j = 0; j < 16; j++) {
            int rowb = j * 8 + lr;
            uint32_t b0, b1, b2, b3, b4, b5, b6, b7;
            LDMX4(b0, b1, b2, b3, bb + SWZ(rowb * 128 + koff));
            LDMX4(b4, b5, b6, b7, bb + SWZ(rowb * 128 + 64 + koff));
            MMA16816(acc[j], afr[0], b0, b1);
            MMA16816(acc[j], afr[1], b2, b3);
            MMA16816(acc[j], afr[2], b4, b5);
            MMA16816(acc[j], afr[3], b6, b7);
        }
        __syncthreads();                     // all reads of buf (t&1) done
        if (t + 2 < NITER) load_b_tile(smb, (t + 2) & 63, t & 1, tid);

        const int tile = t & 63;
        const bool rec = (t >= SEED);
        #pragma unroll
        for (int j = 0; j < 16; j++) {
            int col = tile * 128 + j * 8 + 2 * q;
            float w0 = wsq[col], w1v = wsq[col + 1];
            float s00 = fmaf(acc[j][0], -2.f, w0);
            float s01 = fmaf(acc[j][1], -2.f, w1v);
            float s10 = fmaf(acc[j][2], -2.f, w0);
            float s11 = fmaf(acc[j][3], -2.f, w1v);
            if (rec) {
                if (s00 < thr0) {
                    int slot = atomicAdd(scnt, 1);
                    if (slot < CAP) scand[slot] = (uint32_t)((tt0 << 13) | col);
                }
                if (s01 < thr0) {
                    int slot = atomicAdd(scnt, 1);
                    if (slot < CAP) scand[slot] = (uint32_t)((tt0 << 13) | (col + 1));
                }
                if (s10 < thr1) {
                    int slot = atomicAdd(scnt, 1);
                    if (slot < CAP) scand[slot] = (uint32_t)(((tt0 + 8) << 13) | col);
                }
                if (s11 < thr1) {
                    int slot = atomicAdd(scnt, 1);
                    if (slot < CAP) scand[slot] = (uint32_t)(((tt0 + 8) << 13) | (col + 1));
                }
            }
            run0 = fminf(run0, fminf(s00, s01));
            run1 = fminf(run1, fminf(s10, s11));
        }
        // quad-reduce running min -> token-true threshold for next tile
        #pragma unroll
        for (int o = 1; o <= 2; o <<= 1) {
            run0 = fminf(run0, __shfl_xor_sync(0xFFFFFFFFu, run0, o));
            run1 = fminf(run1, __shfl_xor_sync(0xFFFFFFFFu, run1, o));
        }
        thr0 = run0 + MARGIN;
        thr1 = run1 + MARGIN;
    }
    __syncthreads();

    // =================== cooperative exact refinement ===================
    {
        int cnt = scnt[0];
        if (cnt <= CAP) {
            #pragma unroll 1
            for (int i = tid; i < cnt; i += 256) {
                uint32_t e = scand[i];
                refine_to(skey, zsm, w, wsq, e >> 13, e & 0x1FFF);
            }
        } else {  // overflow net (never expected: seeded threshold)
            #pragma unroll 1
            for (int i = tid; i < 128 * 64; i += 256) {
                int tt = i >> 6, kk = i & 63;
                #pragma unroll 1
                for (int k = kk * 128; k < kk * 128 + 128; k++)
                    refine_to(skey, zsm, w, wsq, tt, k);
            }
        }
    }
    __syncthreads();
    if (tid < 128) sidx[tid] = (int)(skey[tid] & 0xFFFFFFFFull);
    __syncthreads();

    // ---------------- fused combine: z_q scatter, loss, segment sums ----------------
    float lsum = 0.f;
    #pragma unroll 1
    for (int i = tid; i < 8192; i += 256) {
        int tt = i & 127, c = i >> 7;
        int k = sidx[tt];
        float zv = zsm[c * 132 + tt];
        float wv = __ldg(w + k * 64 + c);
        out[OZQ + b * 65536 + c * 1024 + hw0 + tt] = wv;
        float dd = wv - zv;
        lsum += dd * dd;
        atomicAdd(&g_emb[k * 64 + c], zv);
    }
    #pragma unroll
    for (int o = 16; o; o >>= 1) lsum += __shfl_down_sync(0xFFFFFFFFu, lsum, o);
    if (lane == 0) atomicAdd(&g_loss, lsum);
    if (tid < 128) atomicAdd(&g_enc[sidx[tid]], 1.0f);
}

// ------------------------------------------------------------- EMA stage 1
__global__ void k_ema1(const float* __restrict__ cs,
                       const float* __restrict__ ea,
                       float* __restrict__ out) {
    int i = blockIdx.x * blockDim.x + threadIdx.x;
    if (i < NE * DD)
        out[OEA + i] = ea[i] * DECAY + (1.f - DECAY) * g_emb[i];
    float v = 0.f;
    if (i < NE) {
        v = cs[i] * DECAY + (1.f - DECAY) * g_enc[i];
        out[OCS + i] = v;
    }
    #pragma unroll
    for (int o = 16; o; o >>= 1) v += __shfl_down_sync(0xFFFFFFFFu, v, o);
    if ((threadIdx.x & 31) == 0 && i < NE) atomicAdd(&g_nsum, v);
}

// ------------------------------------------------------------- EMA stage 2
__global__ void k_ema2(float* __restrict__ out) {
    int i = blockIdx.x * blockDim.x + threadIdx.x;
    float nn = g_nsum;
    int k = i >> 6;
    float ncs = out[OCS + k];
    float sm  = (ncs + EPSC) / (nn + (float)NE * EPSC) * nn;
    out[OW + i] = out[OEA + i] / sm;
    if (i == 0) out[OLOSS] = BETA * g_loss / (float)(NTOK * DD);
}

// ------------------------------------------------------------- launch
extern "C" void kernel_launch(void* const* d_in, const int* in_sizes, int n_in,
                              void* d_out, int out_size) {
    const float* z  = (const float*)d_in[0];
    const float* w  = (const float*)d_in[1];
    const float* cs = (const float*)d_in[2];
    const float* ea = (const float*)d_in[3];
    float* out = (float*)d_out;

    cudaFuncSetAttribute(k_main, cudaFuncAttributeMaxDynamicSharedMemorySize, SM_TOT);

    k_prep <<<(NE * DD + 255) / 256, 256>>>(w);
    k_wsq  <<<(NE * 32) / 256, 256>>>(w);
    k_main <<<NTOK / 128, 256, SM_TOT>>>(z, w, out);
    k_ema1 <<<(NE * DD) / 256, 256>>>(cs, ea, out);
    k_ema2 <<<(NE * DD) / 256, 256>>>(out);
}